// round 2
// baseline (speedup 1.0000x reference)
#include <cuda_runtime.h>
#include <cuda_bf16.h>

#define BATCH   256
#define IN_DIM  1024
#define WIDTH   64000
#define KOUT    10
#define GROUP   (WIDTH / KOUT)   // 6400
#define NSPLIT  32
#define JSPLIT  (GROUP / NSPLIT) // 200

// Scratch (static device allocations are allowed)
__device__ float  g_xT[IN_DIM * BATCH];        // 1 MB   [dim][batch]
__device__ float  g_bufA[WIDTH * BATCH];       // 65.5MB [neuron][batch]
__device__ float  g_bufB[WIDTH * BATCH];       // 65.5MB
__device__ float4 g_coef[3 * WIDTH];           // 3 MB   per-neuron (c0,c1,c2,c3)
__device__ float  g_part[KOUT * NSPLIT * BATCH];

// ---------------------------------------------------------------------------
// Transpose x (256,1024) row-major -> xT [1024][256]
__global__ void k_transpose(const float* __restrict__ x) {
    int d = blockIdx.x;        // 0..1023
    int b = threadIdx.x;       // 0..255
    g_xT[d * BATCH + b] = x[b * IN_DIM + d];
}

// ---------------------------------------------------------------------------
// Per-neuron coefficients: coef = softmax(w_row) @ GATE_COEF  (hardcoded)
__global__ void k_coef(const float* __restrict__ w1,
                       const float* __restrict__ w2,
                       const float* __restrict__ w3) {
    int tid = blockIdx.x * blockDim.x + threadIdx.x;
    if (tid >= 3 * WIDTH) return;
    int layer = tid / WIDTH;
    int n     = tid - layer * WIDTH;
    const float* w = (layer == 0) ? w1 : (layer == 1) ? w2 : w3;
    w += (size_t)n * 16;

    float v[16];
    float m = -1e30f;
    #pragma unroll
    for (int i = 0; i < 16; i++) { v[i] = w[i]; m = fmaxf(m, v[i]); }
    float s = 0.f;
    #pragma unroll
    for (int i = 0; i < 16; i++) { v[i] = expf(v[i] - m); s += v[i]; }
    float inv = 1.0f / s;
    #pragma unroll
    for (int i = 0; i < 16; i++) v[i] *= inv;

    // GATE_COEF columns combined:
    float c0 = v[8]+v[9]+v[10]+v[11]+v[12]+v[13]+v[14]+v[15];
    float c1 = v[2]+v[3]+v[6]+v[7] - v[8]-v[9]-v[12]-v[13];
    float c2 = v[4]+v[5]+v[6]+v[7] - v[8]-v[9]-v[10]-v[11];
    float c3 = v[1] - v[2] - v[4] - 2.f*v[6] - v[7]
             + v[8] + 2.f*v[9] + v[11] + v[13] - v[14];
    g_coef[tid] = make_float4(c0, c1, c2, c3);
}

// ---------------------------------------------------------------------------
// One logic layer on transposed layout. Warp per neuron, 8 warps/block.
// src selector: 0 = xT, 1 = bufA, 2 = bufB ; same for dst (1 or 2).
__global__ __launch_bounds__(256)
void k_layer(int srcSel, int dstSel, int coefOff,
             const int* __restrict__ ia, const int* __restrict__ ib) {
    int neuron = blockIdx.x * 8 + threadIdx.y;
    int lane   = threadIdx.x;

    const float* src = (srcSel == 0) ? g_xT : (srcSel == 1) ? g_bufA : g_bufB;
    float*       dst = (dstSel == 1) ? g_bufA : g_bufB;

    float4 c = g_coef[coefOff + neuron];
    const float4* __restrict__ pa =
        (const float4*)(src + (size_t)ia[neuron] * BATCH);
    const float4* __restrict__ pb =
        (const float4*)(src + (size_t)ib[neuron] * BATCH);
    float4* __restrict__ po = (float4*)(dst + (size_t)neuron * BATCH);

    // 256 floats = 64 float4 per column; 32 lanes -> 2 iters
    #pragma unroll
    for (int it = 0; it < 2; it++) {
        int i = lane + it * 32;
        float4 av = pa[i];
        float4 bv = pb[i];
        float4 r;
        r.x = fmaf(c.w * av.x, bv.x, fmaf(c.y, av.x, fmaf(c.z, bv.x, c.x)));
        r.y = fmaf(c.w * av.y, bv.y, fmaf(c.y, av.y, fmaf(c.z, bv.y, c.x)));
        r.z = fmaf(c.w * av.z, bv.z, fmaf(c.y, av.z, fmaf(c.z, bv.z, c.x)));
        r.w = fmaf(c.w * av.w, bv.w, fmaf(c.y, av.w, fmaf(c.z, bv.w, c.x)));
        po[i] = r;
    }
}

// ---------------------------------------------------------------------------
// Stage-1 reduce: partial sums over JSPLIT neurons per (k, split, batch)
__global__ __launch_bounds__(256)
void k_preduce() {
    int k = blockIdx.x;   // 0..9
    int s = blockIdx.y;   // 0..31
    int b = threadIdx.x;  // 0..255
    const float* base = g_bufA + ((size_t)(k * GROUP + s * JSPLIT)) * BATCH + b;
    float acc = 0.f;
    #pragma unroll 8
    for (int j = 0; j < JSPLIT; j++) acc += base[(size_t)j * BATCH];
    g_part[(k * NSPLIT + s) * BATCH + b] = acc;
}

// Stage-2: sum NSPLIT partials, scale by 1/TAU, write out[b][k]
__global__ void k_freduce(float* __restrict__ out) {
    int k = blockIdx.x;   // 0..9
    int b = threadIdx.x;  // 0..255
    float acc = 0.f;
    #pragma unroll
    for (int s = 0; s < NSPLIT; s++)
        acc += g_part[(k * NSPLIT + s) * BATCH + b];
    out[b * KOUT + k] = acc * (1.0f / 30.0f);
}

// ---------------------------------------------------------------------------
extern "C" void kernel_launch(void* const* d_in, const int* in_sizes, int n_in,
                              void* d_out, int out_size) {
    const float* x   = (const float*)d_in[0];
    const float* w1  = (const float*)d_in[1];
    const float* w2  = (const float*)d_in[2];
    const float* w3  = (const float*)d_in[3];
    const int*   ia1 = (const int*)d_in[4];
    const int*   ib1 = (const int*)d_in[5];
    const int*   ia2 = (const int*)d_in[6];
    const int*   ib2 = (const int*)d_in[7];
    const int*   ia3 = (const int*)d_in[8];
    const int*   ib3 = (const int*)d_in[9];
    float* out = (float*)d_out;

    k_transpose<<<IN_DIM, BATCH>>>(x);
    k_coef<<<(3 * WIDTH + 255) / 256, 256>>>(w1, w2, w3);

    dim3 lb(32, 8);
    k_layer<<<WIDTH / 8, lb>>>(0, 1, 0,         ia1, ib1);  // xT   -> bufA
    k_layer<<<WIDTH / 8, lb>>>(1, 2, WIDTH,     ia2, ib2);  // bufA -> bufB
    k_layer<<<WIDTH / 8, lb>>>(2, 1, 2 * WIDTH, ia3, ib3);  // bufB -> bufA

    k_preduce<<<dim3(KOUT, NSPLIT), BATCH>>>();
    k_freduce<<<KOUT, BATCH>>>(out);
}

// round 3
// speedup vs baseline: 1.2879x; 1.2879x over previous
#include <cuda_runtime.h>
#include <cuda_fp16.h>

#define BATCH   256
#define IN_DIM  1024
#define WIDTH   64000
#define KOUT    10
#define GROUP   (WIDTH / KOUT)   // 6400
#define NS      64               // splits per group for fused layer3+reduce
#define JS      (GROUP / NS)     // 100 neurons per block

// Scratch — fp16 activations, [neuron][batch] layout, 16B-aligned for uint4 loads
__device__ __align__(256) __half g_xT[IN_DIM * BATCH];     // 0.5 MB
__device__ __align__(256) __half g_bufA[WIDTH * BATCH];    // 32.8 MB
__device__ __align__(256) __half g_bufB[WIDTH * BATCH];    // 32.8 MB
__device__ float4 g_coef[3 * WIDTH];                       // 3 MB
__device__ float  g_part[KOUT * NS * BATCH];

// ---------------------------------------------------------------------------
// Tiled transpose x (256,1024) fp32 -> xT [1024][256] fp16
__global__ void k_transpose(const float* __restrict__ x) {
    __shared__ float tile[32][33];
    int d0 = blockIdx.x * 32;   // dim tile
    int b0 = blockIdx.y * 32;   // batch tile
    // read: rows = batch, cols = dim (coalesced over dim)
    tile[threadIdx.y][threadIdx.x] = x[(size_t)(b0 + threadIdx.y) * IN_DIM + d0 + threadIdx.x];
    __syncthreads();
    // write: rows = dim, cols = batch (coalesced over batch)
    g_xT[(size_t)(d0 + threadIdx.y) * BATCH + b0 + threadIdx.x] =
        __float2half_rn(tile[threadIdx.x][threadIdx.y]);
}

// ---------------------------------------------------------------------------
// Per-neuron coefficients: coef = softmax(w_row) @ GATE_COEF (hardcoded)
__global__ void k_coef(const float* __restrict__ w1,
                       const float* __restrict__ w2,
                       const float* __restrict__ w3) {
    int tid = blockIdx.x * blockDim.x + threadIdx.x;
    if (tid >= 3 * WIDTH) return;
    int layer = tid / WIDTH;
    int n     = tid - layer * WIDTH;
    const float* w = (layer == 0) ? w1 : (layer == 1) ? w2 : w3;
    w += (size_t)n * 16;

    float v[16];
    float m = -1e30f;
    #pragma unroll
    for (int i = 0; i < 16; i++) { v[i] = w[i]; m = fmaxf(m, v[i]); }
    float s = 0.f;
    #pragma unroll
    for (int i = 0; i < 16; i++) { v[i] = __expf(v[i] - m); s += v[i]; }
    float inv = 1.0f / s;
    #pragma unroll
    for (int i = 0; i < 16; i++) v[i] *= inv;

    float c0 = v[8]+v[9]+v[10]+v[11]+v[12]+v[13]+v[14]+v[15];
    float c1 = v[2]+v[3]+v[6]+v[7] - v[8]-v[9]-v[12]-v[13];
    float c2 = v[4]+v[5]+v[6]+v[7] - v[8]-v[9]-v[10]-v[11];
    float c3 = v[1] - v[2] - v[4] - 2.f*v[6] - v[7]
             + v[8] + 2.f*v[9] + v[11] + v[13] - v[14];
    g_coef[tid] = make_float4(c0, c1, c2, c3);
}

// ---------------------------------------------------------------------------
__device__ __forceinline__ __half2 gate_h2(float4 c, __half2 ah, __half2 bh) {
    float2 a = __half22float2(ah);
    float2 b = __half22float2(bh);
    float rx = fmaf(c.w * a.x, b.x, fmaf(c.y, a.x, fmaf(c.z, b.x, c.x)));
    float ry = fmaf(c.w * a.y, b.y, fmaf(c.y, a.y, fmaf(c.z, b.y, c.x)));
    return __floats2half2_rn(rx, ry);
}

// One logic layer, fp16 in/out. Warp per neuron, lane handles 8 halfs (uint4).
// srcSel: 0=xT, 1=bufA, 2=bufB ; dstSel: 1 or 2.
__global__ __launch_bounds__(256)
void k_layer(int srcSel, int dstSel, int coefOff,
             const int* __restrict__ ia, const int* __restrict__ ib) {
    int neuron = blockIdx.x * 8 + threadIdx.y;
    int lane   = threadIdx.x;

    const __half* src = (srcSel == 0) ? g_xT : (srcSel == 1) ? g_bufA : g_bufB;
    __half*       dst = (dstSel == 1) ? g_bufA : g_bufB;

    float4 c = g_coef[coefOff + neuron];
    const uint4* __restrict__ pa = (const uint4*)(src + (size_t)ia[neuron] * BATCH);
    const uint4* __restrict__ pb = (const uint4*)(src + (size_t)ib[neuron] * BATCH);
    uint4* __restrict__ po = (uint4*)(dst + (size_t)neuron * BATCH);

    // 256 halfs = 512B per column = 32 lanes x 16B -> exactly one uint4 per lane
    uint4 av = pa[lane];
    uint4 bv = pb[lane];
    uint4 r;
    ((__half2*)&r)[0] = gate_h2(c, ((__half2*)&av)[0], ((__half2*)&bv)[0]);
    ((__half2*)&r)[1] = gate_h2(c, ((__half2*)&av)[1], ((__half2*)&bv)[1]);
    ((__half2*)&r)[2] = gate_h2(c, ((__half2*)&av)[2], ((__half2*)&bv)[2]);
    ((__half2*)&r)[3] = gate_h2(c, ((__half2*)&av)[3], ((__half2*)&bv)[3]);
    po[lane] = r;
}

// ---------------------------------------------------------------------------
// Fused layer-3 + partial group sum. Block = 128 threads (one half2 batch pair
// each), handles JS=100 consecutive neurons of one (k, split). fp32 accum.
__global__ __launch_bounds__(128)
void k_layer3_reduce(const int* __restrict__ ia, const int* __restrict__ ib) {
    int k = blockIdx.x;       // 0..9
    int s = blockIdx.y;       // 0..NS-1
    int t = threadIdx.x;      // 0..127 -> batch pair
    const __half2* __restrict__ src = (const __half2*)g_bufB;  // layer-2 out

    int n0 = k * GROUP + s * JS;
    float accx = 0.f, accy = 0.f;

    #pragma unroll 4
    for (int j = 0; j < JS; j++) {
        int n = n0 + j;
        float4 c = g_coef[2 * WIDTH + n];
        int A = __ldg(&ia[n]);
        int B = __ldg(&ib[n]);
        float2 a = __half22float2(src[(size_t)A * (BATCH/2) + t]);
        float2 b = __half22float2(src[(size_t)B * (BATCH/2) + t]);
        accx += fmaf(c.w * a.x, b.x, fmaf(c.y, a.x, fmaf(c.z, b.x, c.x)));
        accy += fmaf(c.w * a.y, b.y, fmaf(c.y, a.y, fmaf(c.z, b.y, c.x)));
    }
    float* p = g_part + (size_t)(k * NS + s) * BATCH + 2 * t;
    p[0] = accx;
    p[1] = accy;
}

// Stage-2: sum NS partials, scale by 1/TAU, write out[b][k]
__global__ void k_freduce(float* __restrict__ out) {
    int k = blockIdx.x;   // 0..9
    int b = threadIdx.x;  // 0..255
    float acc = 0.f;
    #pragma unroll
    for (int s = 0; s < NS; s++)
        acc += g_part[(size_t)(k * NS + s) * BATCH + b];
    out[b * KOUT + k] = acc * (1.0f / 30.0f);
}

// ---------------------------------------------------------------------------
extern "C" void kernel_launch(void* const* d_in, const int* in_sizes, int n_in,
                              void* d_out, int out_size) {
    const float* x   = (const float*)d_in[0];
    const float* w1  = (const float*)d_in[1];
    const float* w2  = (const float*)d_in[2];
    const float* w3  = (const float*)d_in[3];
    const int*   ia1 = (const int*)d_in[4];
    const int*   ib1 = (const int*)d_in[5];
    const int*   ia2 = (const int*)d_in[6];
    const int*   ib2 = (const int*)d_in[7];
    const int*   ia3 = (const int*)d_in[8];
    const int*   ib3 = (const int*)d_in[9];
    float* out = (float*)d_out;

    k_transpose<<<dim3(IN_DIM / 32, BATCH / 32), dim3(32, 32)>>>(x);
    k_coef<<<(3 * WIDTH + 255) / 256, 256>>>(w1, w2, w3);

    dim3 lb(32, 8);
    k_layer<<<WIDTH / 8, lb>>>(0, 1, 0,     ia1, ib1);  // xT   -> bufA
    k_layer<<<WIDTH / 8, lb>>>(1, 2, WIDTH, ia2, ib2);  // bufA -> bufB

    k_layer3_reduce<<<dim3(KOUT, NS), 128>>>(ia3, ib3); // bufB -> partials
    k_freduce<<<KOUT, BATCH>>>(out);
}

// round 4
// speedup vs baseline: 1.9358x; 1.5030x over previous
#include <cuda_runtime.h>
#include <cuda_fp16.h>

#define BATCH   256
#define IN_DIM  1024
#define WIDTH   64000
#define KOUT    10
#define GROUP   (WIDTH / KOUT)   // 6400
#define NS      64               // splits per group for fused layer3+reduce
#define JS      (GROUP / NS)     // 100 neurons per block

// Scratch — fp16 activations, [neuron][batch] layout, 16B-aligned
__device__ __align__(256) __half g_xT[IN_DIM * BATCH];     // 0.5 MB
__device__ __align__(256) __half g_bufA[WIDTH * BATCH];    // 32.8 MB
__device__ __align__(256) __half g_bufB[WIDTH * BATCH];    // 32.8 MB
__device__ float4 g_coef[3 * WIDTH];                       // 3 MB
__device__ float  g_part[KOUT * NS * BATCH];

// ---------------------------------------------------------------------------
// Tiled transpose x (256,1024) fp32 -> xT [1024][256] fp16
__global__ void k_transpose(const float* __restrict__ x) {
    __shared__ float tile[32][33];
    int d0 = blockIdx.x * 32;
    int b0 = blockIdx.y * 32;
    tile[threadIdx.y][threadIdx.x] =
        x[(size_t)(b0 + threadIdx.y) * IN_DIM + d0 + threadIdx.x];
    __syncthreads();
    g_xT[(size_t)(d0 + threadIdx.y) * BATCH + b0 + threadIdx.x] =
        __float2half_rn(tile[threadIdx.x][threadIdx.y]);
}

// ---------------------------------------------------------------------------
// Per-neuron coefficients: coef = softmax(w_row) @ GATE_COEF (hardcoded)
__global__ void k_coef(const float* __restrict__ w1,
                       const float* __restrict__ w2,
                       const float* __restrict__ w3) {
    int tid = blockIdx.x * blockDim.x + threadIdx.x;
    if (tid >= 3 * WIDTH) return;
    int layer = tid / WIDTH;
    int n     = tid - layer * WIDTH;
    const float* w = (layer == 0) ? w1 : (layer == 1) ? w2 : w3;
    w += (size_t)n * 16;

    float v[16];
    float m = -1e30f;
    #pragma unroll
    for (int i = 0; i < 16; i++) { v[i] = w[i]; m = fmaxf(m, v[i]); }
    float s = 0.f;
    #pragma unroll
    for (int i = 0; i < 16; i++) { v[i] = __expf(v[i] - m); s += v[i]; }
    float inv = 1.0f / s;
    #pragma unroll
    for (int i = 0; i < 16; i++) v[i] *= inv;

    float c0 = v[8]+v[9]+v[10]+v[11]+v[12]+v[13]+v[14]+v[15];
    float c1 = v[2]+v[3]+v[6]+v[7] - v[8]-v[9]-v[12]-v[13];
    float c2 = v[4]+v[5]+v[6]+v[7] - v[8]-v[9]-v[10]-v[11];
    float c3 = v[1] - v[2] - v[4] - 2.f*v[6] - v[7]
             + v[8] + 2.f*v[9] + v[11] + v[13] - v[14];
    g_coef[tid] = make_float4(c0, c1, c2, c3);
}

// ---------------------------------------------------------------------------
__device__ __forceinline__ __half2 gate_h2(float4 c, __half2 ah, __half2 bh) {
    float2 a = __half22float2(ah);
    float2 b = __half22float2(bh);
    float rx = fmaf(c.w * a.x, b.x, fmaf(c.y, a.x, fmaf(c.z, b.x, c.x)));
    float ry = fmaf(c.w * a.y, b.y, fmaf(c.y, a.y, fmaf(c.z, b.y, c.x)));
    return __floats2half2_rn(rx, ry);
}

__device__ __forceinline__ uint4 gate_u4(float4 c, uint4 av, uint4 bv) {
    uint4 r;
    ((__half2*)&r)[0] = gate_h2(c, ((__half2*)&av)[0], ((__half2*)&bv)[0]);
    ((__half2*)&r)[1] = gate_h2(c, ((__half2*)&av)[1], ((__half2*)&bv)[1]);
    ((__half2*)&r)[2] = gate_h2(c, ((__half2*)&av)[2], ((__half2*)&bv)[2]);
    ((__half2*)&r)[3] = gate_h2(c, ((__half2*)&av)[3], ((__half2*)&bv)[3]);
    return r;
}

// One logic layer, fp16 in/out. TWO neurons per warp (double the gather MLP).
// srcSel: 0=xT, 1=bufA, 2=bufB ; dstSel: 1 or 2.
__global__ __launch_bounds__(256)
void k_layer(int srcSel, int dstSel, int coefOff,
             const int* __restrict__ ia, const int* __restrict__ ib) {
    int warp = blockIdx.x * 8 + threadIdx.y;
    int n0   = warp * 2;
    int n1   = n0 + 1;
    int lane = threadIdx.x;

    const __half* src = (srcSel == 0) ? g_xT : (srcSel == 1) ? g_bufA : g_bufB;
    __half*       dst = (dstSel == 1) ? g_bufA : g_bufB;

    // Batch the 4 index loads (independent, all in flight together)
    int A0 = __ldg(ia + n0), B0 = __ldg(ib + n0);
    int A1 = __ldg(ia + n1), B1 = __ldg(ib + n1);
    float4 c0 = g_coef[coefOff + n0];
    float4 c1 = g_coef[coefOff + n1];

    // 4 independent 16B gathers in flight per lane
    uint4 a0 = ((const uint4*)(src + (size_t)A0 * BATCH))[lane];
    uint4 b0 = ((const uint4*)(src + (size_t)B0 * BATCH))[lane];
    uint4 a1 = ((const uint4*)(src + (size_t)A1 * BATCH))[lane];
    uint4 b1 = ((const uint4*)(src + (size_t)B1 * BATCH))[lane];

    ((uint4*)(dst + (size_t)n0 * BATCH))[lane] = gate_u4(c0, a0, b0);
    ((uint4*)(dst + (size_t)n1 * BATCH))[lane] = gate_u4(c1, a1, b1);
}

// ---------------------------------------------------------------------------
// Fused layer-3 + partial group sum. Warp-per-neuron with uint4 (16B) loads.
// Block = 4 warps; warp w handles neurons j = w, w+4, ... of its (k,s) slice.
// Each lane accumulates 8 batch elements in fp32; smem reduce across warps.
__global__ __launch_bounds__(128)
void k_layer3_reduce(const int* __restrict__ ia, const int* __restrict__ ib) {
    int k    = blockIdx.x;            // 0..9
    int s    = blockIdx.y;            // 0..NS-1
    int w    = threadIdx.x >> 5;      // 0..3
    int lane = threadIdx.x & 31;

    const __half* src = g_bufB;       // layer-2 output
    int n0 = k * GROUP + s * JS;

    float acc[8] = {0.f,0.f,0.f,0.f,0.f,0.f,0.f,0.f};

    #pragma unroll 2
    for (int j = w; j < JS; j += 4) {
        int n = n0 + j;
        int A = __ldg(ia + n);
        int B = __ldg(ib + n);
        float4 c = g_coef[2 * WIDTH + n];
        uint4 av = ((const uint4*)(src + (size_t)A * BATCH))[lane];
        uint4 bv = ((const uint4*)(src + (size_t)B * BATCH))[lane];
        #pragma unroll
        for (int h = 0; h < 4; h++) {
            float2 a = __half22float2(((__half2*)&av)[h]);
            float2 b = __half22float2(((__half2*)&bv)[h]);
            acc[2*h]   += fmaf(c.w * a.x, b.x, fmaf(c.y, a.x, fmaf(c.z, b.x, c.x)));
            acc[2*h+1] += fmaf(c.w * a.y, b.y, fmaf(c.y, a.y, fmaf(c.z, b.y, c.x)));
        }
    }

    __shared__ float part[4][BATCH];
    #pragma unroll
    for (int i = 0; i < 8; i++) part[w][lane * 8 + i] = acc[i];
    __syncthreads();

    int t = threadIdx.x;
    #pragma unroll
    for (int col = t; col < BATCH; col += 128) {
        float v = part[0][col] + part[1][col] + part[2][col] + part[3][col];
        g_part[(size_t)(k * NS + s) * BATCH + col] = v;
    }
}

// Stage-2: sum NS partials, scale by 1/TAU, write out[b][k]
__global__ void k_freduce(float* __restrict__ out) {
    int k = blockIdx.x;   // 0..9
    int b = threadIdx.x;  // 0..255
    float acc = 0.f;
    #pragma unroll
    for (int s = 0; s < NS; s++)
        acc += g_part[(size_t)(k * NS + s) * BATCH + b];
    out[b * KOUT + k] = acc * (1.0f / 30.0f);
}

// ---------------------------------------------------------------------------
extern "C" void kernel_launch(void* const* d_in, const int* in_sizes, int n_in,
                              void* d_out, int out_size) {
    const float* x   = (const float*)d_in[0];
    const float* w1  = (const float*)d_in[1];
    const float* w2  = (const float*)d_in[2];
    const float* w3  = (const float*)d_in[3];
    const int*   ia1 = (const int*)d_in[4];
    const int*   ib1 = (const int*)d_in[5];
    const int*   ia2 = (const int*)d_in[6];
    const int*   ib2 = (const int*)d_in[7];
    const int*   ia3 = (const int*)d_in[8];
    const int*   ib3 = (const int*)d_in[9];
    float* out = (float*)d_out;

    k_transpose<<<dim3(IN_DIM / 32, BATCH / 32), dim3(32, 32)>>>(x);
    k_coef<<<(3 * WIDTH + 255) / 256, 256>>>(w1, w2, w3);

    dim3 lb(32, 8);
    k_layer<<<WIDTH / 16, lb>>>(0, 1, 0,     ia1, ib1);  // xT   -> bufA
    k_layer<<<WIDTH / 16, lb>>>(1, 2, WIDTH, ia2, ib2);  // bufA -> bufB

    k_layer3_reduce<<<dim3(KOUT, NS), 128>>>(ia3, ib3);  // bufB -> partials
    k_freduce<<<KOUT, BATCH>>>(out);
}

// round 5
// speedup vs baseline: 2.1295x; 1.1001x over previous
#include <cuda_runtime.h>
#include <cuda_fp16.h>

#define BATCH   256
#define IN_DIM  1024
#define WIDTH   64000
#define KOUT    10
#define GROUP   (WIDTH / KOUT)   // 6400
#define NS      80               // splits per group for fused layer3+reduce
#define JS      (GROUP / NS)     // 80 neurons per block
#define L3WARPS 8
#define JW      (JS / L3WARPS)   // 10 neurons per warp

// Scratch — fp16 activations, [neuron][batch] layout, 16B-aligned
__device__ __align__(256) __half g_xT[IN_DIM * BATCH];     // 0.5 MB
__device__ __align__(256) __half g_bufA[WIDTH * BATCH];    // 32.8 MB
__device__ __align__(256) __half g_bufB[WIDTH * BATCH];    // 32.8 MB
__device__ float4 g_coef[3 * WIDTH];                       // 3 MB
__device__ float  g_part[KOUT * NS * BATCH];               // 800 KB

// ---------------------------------------------------------------------------
// Tiled transpose x (256,1024) fp32 -> xT [1024][256] fp16
__global__ void k_transpose(const float* __restrict__ x) {
    __shared__ float tile[32][33];
    int d0 = blockIdx.x * 32;
    int b0 = blockIdx.y * 32;
    tile[threadIdx.y][threadIdx.x] =
        x[(size_t)(b0 + threadIdx.y) * IN_DIM + d0 + threadIdx.x];
    __syncthreads();
    g_xT[(size_t)(d0 + threadIdx.y) * BATCH + b0 + threadIdx.x] =
        __float2half_rn(tile[threadIdx.x][threadIdx.y]);
}

// ---------------------------------------------------------------------------
// Per-neuron coefficients: coef = softmax(w_row) @ GATE_COEF (hardcoded)
__global__ void k_coef(const float* __restrict__ w1,
                       const float* __restrict__ w2,
                       const float* __restrict__ w3) {
    int tid = blockIdx.x * blockDim.x + threadIdx.x;
    if (tid >= 3 * WIDTH) return;
    int layer = tid / WIDTH;
    int n     = tid - layer * WIDTH;
    const float* w = (layer == 0) ? w1 : (layer == 1) ? w2 : w3;
    w += (size_t)n * 16;

    float v[16];
    float m = -1e30f;
    #pragma unroll
    for (int i = 0; i < 16; i++) { v[i] = w[i]; m = fmaxf(m, v[i]); }
    float s = 0.f;
    #pragma unroll
    for (int i = 0; i < 16; i++) { v[i] = __expf(v[i] - m); s += v[i]; }
    float inv = 1.0f / s;
    #pragma unroll
    for (int i = 0; i < 16; i++) v[i] *= inv;

    float c0 = v[8]+v[9]+v[10]+v[11]+v[12]+v[13]+v[14]+v[15];
    float c1 = v[2]+v[3]+v[6]+v[7] - v[8]-v[9]-v[12]-v[13];
    float c2 = v[4]+v[5]+v[6]+v[7] - v[8]-v[9]-v[10]-v[11];
    float c3 = v[1] - v[2] - v[4] - 2.f*v[6] - v[7]
             + v[8] + 2.f*v[9] + v[11] + v[13] - v[14];
    g_coef[tid] = make_float4(c0, c1, c2, c3);
}

// ---------------------------------------------------------------------------
__device__ __forceinline__ __half2 gate_h2(float4 c, __half2 ah, __half2 bh) {
    float2 a = __half22float2(ah);
    float2 b = __half22float2(bh);
    float rx = fmaf(c.w * a.x, b.x, fmaf(c.y, a.x, fmaf(c.z, b.x, c.x)));
    float ry = fmaf(c.w * a.y, b.y, fmaf(c.y, a.y, fmaf(c.z, b.y, c.x)));
    return __floats2half2_rn(rx, ry);
}

__device__ __forceinline__ uint4 gate_u4(float4 c, uint4 av, uint4 bv) {
    uint4 r;
    ((__half2*)&r)[0] = gate_h2(c, ((__half2*)&av)[0], ((__half2*)&bv)[0]);
    ((__half2*)&r)[1] = gate_h2(c, ((__half2*)&av)[1], ((__half2*)&bv)[1]);
    ((__half2*)&r)[2] = gate_h2(c, ((__half2*)&av)[2], ((__half2*)&bv)[2]);
    ((__half2*)&r)[3] = gate_h2(c, ((__half2*)&av)[3], ((__half2*)&bv)[3]);
    return r;
}

// One logic layer, fp16 in/out. FOUR neurons per warp (8 gathers in flight).
// srcSel: 0=xT, 1=bufA, 2=bufB ; dstSel: 1 or 2.
__global__ __launch_bounds__(256)
void k_layer(int srcSel, int dstSel, int coefOff,
             const int* __restrict__ ia, const int* __restrict__ ib) {
    int warp = blockIdx.x * 8 + threadIdx.y;
    int n0   = warp * 4;
    int lane = threadIdx.x;

    const __half* src = (srcSel == 0) ? g_xT : (srcSel == 1) ? g_bufA : g_bufB;
    __half*       dst = (dstSel == 1) ? g_bufA : g_bufB;

    // Batch all index loads (8 independent loads in flight)
    int A[4], B[4];
    #pragma unroll
    for (int q = 0; q < 4; q++) {
        A[q] = __ldg(ia + n0 + q);
        B[q] = __ldg(ib + n0 + q);
    }

    // 8 independent 16B gathers in flight per lane
    uint4 av[4], bv[4];
    #pragma unroll
    for (int q = 0; q < 4; q++) {
        av[q] = ((const uint4*)(src + (size_t)A[q] * BATCH))[lane];
        bv[q] = ((const uint4*)(src + (size_t)B[q] * BATCH))[lane];
    }

    #pragma unroll
    for (int q = 0; q < 4; q++) {
        float4 c = g_coef[coefOff + n0 + q];
        ((uint4*)(dst + (size_t)(n0 + q) * BATCH))[lane] = gate_u4(c, av[q], bv[q]);
    }
}

// ---------------------------------------------------------------------------
// Fused layer-3 + partial group sum. 8 warps/block, warp-per-neuron uint4
// loads, JW=10 consecutive neurons per warp, fp32 accumulation.
__global__ __launch_bounds__(256)
void k_layer3_reduce(const int* __restrict__ ia, const int* __restrict__ ib) {
    int k    = blockIdx.x;            // 0..9
    int s    = blockIdx.y;            // 0..NS-1
    int w    = threadIdx.x >> 5;      // 0..7
    int lane = threadIdx.x & 31;

    const __half* src = g_bufB;       // layer-2 output
    int n0 = k * GROUP + s * JS + w * JW;

    float acc[8] = {0.f,0.f,0.f,0.f,0.f,0.f,0.f,0.f};

    #pragma unroll 2
    for (int j = 0; j < JW; j++) {
        int n = n0 + j;
        int A = __ldg(ia + n);
        int B = __ldg(ib + n);
        float4 c = g_coef[2 * WIDTH + n];
        uint4 av = ((const uint4*)(src + (size_t)A * BATCH))[lane];
        uint4 bv = ((const uint4*)(src + (size_t)B * BATCH))[lane];
        #pragma unroll
        for (int h = 0; h < 4; h++) {
            float2 a = __half22float2(((__half2*)&av)[h]);
            float2 b = __half22float2(((__half2*)&bv)[h]);
            acc[2*h]   += fmaf(c.w * a.x, b.x, fmaf(c.y, a.x, fmaf(c.z, b.x, c.x)));
            acc[2*h+1] += fmaf(c.w * a.y, b.y, fmaf(c.y, a.y, fmaf(c.z, b.y, c.x)));
        }
    }

    __shared__ float part[L3WARPS][BATCH];
    #pragma unroll
    for (int i = 0; i < 8; i++) part[w][lane * 8 + i] = acc[i];
    __syncthreads();

    // 256 threads: one batch column each, sum the 8 warp partials
    int col = threadIdx.x;
    float v = 0.f;
    #pragma unroll
    for (int i = 0; i < L3WARPS; i++) v += part[i][col];
    g_part[(size_t)(k * NS + s) * BATCH + col] = v;
}

// Stage-2: sum NS partials, scale by 1/TAU, write out[b][k]
__global__ void k_freduce(float* __restrict__ out) {
    int k = blockIdx.x;   // 0..9
    int b = threadIdx.x;  // 0..255
    float acc = 0.f;
    #pragma unroll
    for (int s = 0; s < NS; s++)
        acc += g_part[(size_t)(k * NS + s) * BATCH + b];
    out[b * KOUT + k] = acc * (1.0f / 30.0f);
}

// ---------------------------------------------------------------------------
extern "C" void kernel_launch(void* const* d_in, const int* in_sizes, int n_in,
                              void* d_out, int out_size) {
    const float* x   = (const float*)d_in[0];
    const float* w1  = (const float*)d_in[1];
    const float* w2  = (const float*)d_in[2];
    const float* w3  = (const float*)d_in[3];
    const int*   ia1 = (const int*)d_in[4];
    const int*   ib1 = (const int*)d_in[5];
    const int*   ia2 = (const int*)d_in[6];
    const int*   ib2 = (const int*)d_in[7];
    const int*   ia3 = (const int*)d_in[8];
    const int*   ib3 = (const int*)d_in[9];
    float* out = (float*)d_out;

    k_transpose<<<dim3(IN_DIM / 32, BATCH / 32), dim3(32, 32)>>>(x);
    k_coef<<<(3 * WIDTH + 255) / 256, 256>>>(w1, w2, w3);

    dim3 lb(32, 8);
    k_layer<<<WIDTH / 32, lb>>>(0, 1, 0,     ia1, ib1);  // xT   -> bufA
    k_layer<<<WIDTH / 32, lb>>>(1, 2, WIDTH, ia2, ib2);  // bufA -> bufB

    k_layer3_reduce<<<dim3(KOUT, NS), 256>>>(ia3, ib3);  // bufB -> partials
    k_freduce<<<KOUT, BATCH>>>(out);
}